// round 1
// baseline (speedup 1.0000x reference)
#include <cuda_runtime.h>
#include <cstdint>

#define D      64
#define TQ     64
#define TI     32
#define NSPLIT 16
#define MAXB   2048
#define MAXN   20000
#define MAXL   100

// ---------------- static device scratch (no allocations allowed) ----------------
__device__ float g_xnorm[MAXB];
__device__ float g_snorm[MAXN];
__device__ float g_f1norm[MAXN];
__device__ float g_f2norm[MAXN];
__device__ int   g_match[MAXB];
__device__ float g_pnum[(size_t)NSPLIT * MAXB * 128];   // pass1 partial numerators (f1|f2)
__device__ float g_pden[(size_t)NSPLIT * MAXB];
__device__ float g_xt1[MAXB * D];
__device__ float g_xt2[MAXB * D];
__device__ float g_xtn1[MAXB];
__device__ float g_xtn2[MAXB];
__device__ int   g_yidx1[MAXB];
__device__ int   g_yidx2[MAXB];
__device__ float g_pout[(size_t)2 * NSPLIT * MAXB * 32];
__device__ float g_pden2[(size_t)2 * NSPLIT * MAXB];

// ---------------- K0: row norms + match init ----------------
__global__ void norms_kernel(const float* __restrict__ x, const float* __restrict__ sf,
                             const float* __restrict__ f1, const float* __restrict__ f2,
                             int B, int N) {
    int r = blockIdx.x * blockDim.x + threadIdx.x;
    int total = 3 * N + B;
    if (r >= total) return;
    const float* src; float* dst; int row;
    if (r < N)            { src = sf; row = r;         dst = g_snorm; }
    else if (r < 2 * N)   { src = f1; row = r - N;     dst = g_f1norm; }
    else if (r < 3 * N)   { src = f2; row = r - 2 * N; dst = g_f2norm; }
    else                  { src = x;  row = r - 3 * N; dst = g_xnorm; g_match[row] = 0x7fffffff; }
    const float4* p = (const float4*)(src + (size_t)row * D);
    float s = 0.f;
#pragma unroll
    for (int k = 0; k < 16; k++) {
        float4 v = p[k];
        s = fmaf(v.x, v.x, fmaf(v.y, v.y, fmaf(v.z, v.z, fmaf(v.w, v.w, s))));
    }
    dst[row] = s;
}

// ---------------- Pass 1 ----------------
struct SmemP1 {
    float Qs[TQ][D + 4];      // x tile [q][d]
    float qn[TQ];
    float Kst[D][TI + 4];     // star tile transposed [d][j]
    float kn[TI];
    float Es[TI][TQ + 4];     // weights transposed [j][q]
    float Vs[TI][128 + 4];    // [j][ f1(64) | f2(64) ]
};

__global__ void __launch_bounds__(256) pass1_kernel(
    const float* __restrict__ x, const float* __restrict__ sf,
    const float* __restrict__ f1, const float* __restrict__ f2,
    int B, int N)
{
    extern __shared__ char smraw[];
    SmemP1& sm = *reinterpret_cast<SmemP1*>(smraw);
    int t = threadIdx.x, tx = t & 15, ty = t >> 4;
    int qbase = blockIdx.x * TQ;
    int chunk = (N + NSPLIT - 1) / NSPLIT;
    int i0base = blockIdx.y * chunk;
    int iend = min(i0base + chunk, N);

    { // load Q tile + norms (once)
        int row = t >> 2, cg = (t & 3) * 16;
        const float4* src = (const float4*)(x + (size_t)(qbase + row) * D + cg);
        float4* dst = (float4*)&sm.Qs[row][cg];
        dst[0] = src[0]; dst[1] = src[1]; dst[2] = src[2]; dst[3] = src[3];
        if (t < TQ) sm.qn[t] = g_xnorm[qbase + t];
    }

    float C[4][8];
#pragma unroll
    for (int a = 0; a < 4; a++)
#pragma unroll
        for (int b = 0; b < 8; b++) C[a][b] = 0.f;
    float denp[4] = {0.f, 0.f, 0.f, 0.f};
    int mmin[4] = {0x7fffffff, 0x7fffffff, 0x7fffffff, 0x7fffffff};

    for (int i0 = i0base; i0 < iend; i0 += TI) {
        __syncthreads();  // prior-tile Es/Vs reads done; Qs visible (first iter)
        { // K tile transposed + norms
            int j = t >> 3, dg = (t & 7) * 8;
            int i = i0 + j;
            float4 a = {0,0,0,0}, b = {0,0,0,0};
            if (i < iend) {
                a = *(const float4*)(sf + (size_t)i * D + dg);
                b = *(const float4*)(sf + (size_t)i * D + dg + 4);
            }
            sm.Kst[dg + 0][j] = a.x; sm.Kst[dg + 1][j] = a.y;
            sm.Kst[dg + 2][j] = a.z; sm.Kst[dg + 3][j] = a.w;
            sm.Kst[dg + 4][j] = b.x; sm.Kst[dg + 5][j] = b.y;
            sm.Kst[dg + 6][j] = b.z; sm.Kst[dg + 7][j] = b.w;
            if (t < TI) sm.kn[t] = (i0 + t < iend) ? g_snorm[i0 + t] : 1e30f;
        }
        { // V tile: [f1 | f2]
            int j = t >> 3, cg = (t & 7) * 16;
            int i = i0 + j;
#pragma unroll
            for (int k = 0; k < 4; k++) {
                int c = cg + k * 4;
                float4 v = {0,0,0,0};
                if (i < iend)
                    v = (c < 64) ? *(const float4*)(f1 + (size_t)i * D + c)
                                 : *(const float4*)(f2 + (size_t)i * D + (c - 64));
                *(float4*)&sm.Vs[j][c] = v;
            }
        }
        __syncthreads();

        // step 1: 64x32x64 dot tile
        float acc[4][2] = {{0.f,0.f},{0.f,0.f},{0.f,0.f},{0.f,0.f}};
#pragma unroll
        for (int d = 0; d < D; d += 4) {
            float2 b0 = *(const float2*)&sm.Kst[d + 0][tx * 2];
            float2 b1 = *(const float2*)&sm.Kst[d + 1][tx * 2];
            float2 b2 = *(const float2*)&sm.Kst[d + 2][tx * 2];
            float2 b3 = *(const float2*)&sm.Kst[d + 3][tx * 2];
#pragma unroll
            for (int qq = 0; qq < 4; qq++) {
                float4 a = *(const float4*)&sm.Qs[ty * 4 + qq][d];
                acc[qq][0] = fmaf(a.x, b0.x, fmaf(a.y, b1.x, fmaf(a.z, b2.x, fmaf(a.w, b3.x, acc[qq][0]))));
                acc[qq][1] = fmaf(a.x, b0.y, fmaf(a.y, b1.y, fmaf(a.z, b2.y, fmaf(a.w, b3.y, acc[qq][1]))));
            }
        }
        // exp + E store + den/match partials
#pragma unroll
        for (int jj = 0; jj < 2; jj++) {
            int j = tx * 2 + jj;
#pragma unroll
            for (int qq = 0; qq < 4; qq++) {
                int q = ty * 4 + qq;
                float raw = sm.qn[q] + sm.kn[j] - 2.0f * acc[qq][jj];
                if (raw <= 0.0f) mmin[qq] = min(mmin[qq], i0 + j);
                float e = __expf(-fmaxf(raw, 0.0f));
                sm.Es[j][q] = e;
                denp[qq] += e;
            }
        }
        __syncthreads();

        // step 2: C[64q][128d] += E[64x32] @ V[32x128]
#pragma unroll 4
        for (int j = 0; j < TI; j++) {
            float4 ev = *(const float4*)&sm.Es[j][ty * 4];
            float2 v0 = *(const float2*)&sm.Vs[j][      tx * 2];
            float2 v1 = *(const float2*)&sm.Vs[j][32  + tx * 2];
            float2 v2 = *(const float2*)&sm.Vs[j][64  + tx * 2];
            float2 v3 = *(const float2*)&sm.Vs[j][96  + tx * 2];
            float ee[4] = {ev.x, ev.y, ev.z, ev.w};
#pragma unroll
            for (int qq = 0; qq < 4; qq++) {
                C[qq][0] = fmaf(ee[qq], v0.x, C[qq][0]);
                C[qq][1] = fmaf(ee[qq], v0.y, C[qq][1]);
                C[qq][2] = fmaf(ee[qq], v1.x, C[qq][2]);
                C[qq][3] = fmaf(ee[qq], v1.y, C[qq][3]);
                C[qq][4] = fmaf(ee[qq], v2.x, C[qq][4]);
                C[qq][5] = fmaf(ee[qq], v2.y, C[qq][5]);
                C[qq][6] = fmaf(ee[qq], v3.x, C[qq][6]);
                C[qq][7] = fmaf(ee[qq], v3.y, C[qq][7]);
            }
        }
    }

    // epilogue: partial numerators, den + match reductions over tx
#pragma unroll
    for (int qq = 0; qq < 4; qq++) {
        int q = qbase + ty * 4 + qq;
        size_t base = ((size_t)blockIdx.y * B + q) * 128;
#pragma unroll
        for (int dd = 0; dd < 4; dd++) {
            int d = dd * 32 + tx * 2;
            g_pnum[base + d]     = C[qq][dd * 2 + 0];
            g_pnum[base + d + 1] = C[qq][dd * 2 + 1];
        }
        float v = denp[qq];
#pragma unroll
        for (int o = 8; o; o >>= 1) v += __shfl_xor_sync(0xffffffffu, v, o);
        int mv = mmin[qq];
#pragma unroll
        for (int o = 8; o; o >>= 1) mv = min(mv, __shfl_xor_sync(0xffffffffu, mv, o));
        if (tx == 0) {
            g_pden[(size_t)blockIdx.y * B + q] = v;
            if (mv != 0x7fffffff) atomicMin(&g_match[q], mv);
        }
    }
}

// ---------------- K2: reduce -> xt, y = xt W + b, argmin labels ----------------
__global__ void mid_kernel(const float* __restrict__ f1, const float* __restrict__ f2,
                           const float* __restrict__ W1, const float* __restrict__ b1,
                           const float* __restrict__ W2, const float* __restrict__ b2,
                           const float* __restrict__ u1, const float* __restrict__ u2,
                           int B, int N, int DY, int L) {
    __shared__ float sxt[8][2][D];
    __shared__ float sy[8][2][32];
    int wl = threadIdx.x >> 5;
    int lane = threadIdx.x & 31;
    int b = blockIdx.x * 8 + wl;
    if (b >= B) return;

    float den = 0.f;
#pragma unroll
    for (int s = 0; s < NSPLIT; s++) den += g_pden[(size_t)s * B + b];
    int d0 = lane, d1 = lane + 32;
    float n10 = 0, n11 = 0, n20 = 0, n21 = 0;
#pragma unroll
    for (int s = 0; s < NSPLIT; s++) {
        const float* p = g_pnum + ((size_t)s * B + b) * 128;
        n10 += p[d0]; n11 += p[d1]; n20 += p[64 + d0]; n21 += p[64 + d1];
    }
    float inv = 1.0f / den;
    float x10 = n10 * inv, x11 = n11 * inv, x20 = n20 * inv, x21 = n21 * inv;
    int m = g_match[b];
    if (m < N) {
        x10 = f1[(size_t)m * D + d0]; x11 = f1[(size_t)m * D + d1];
        x20 = f2[(size_t)m * D + d0]; x21 = f2[(size_t)m * D + d1];
    }
    g_xt1[b * D + d0] = x10; g_xt1[b * D + d1] = x11;
    g_xt2[b * D + d0] = x20; g_xt2[b * D + d1] = x21;
    sxt[wl][0][d0] = x10; sxt[wl][0][d1] = x11;
    sxt[wl][1][d0] = x20; sxt[wl][1][d1] = x21;
    float nr1 = x10 * x10 + x11 * x11;
    float nr2 = x20 * x20 + x21 * x21;
#pragma unroll
    for (int o = 16; o; o >>= 1) {
        nr1 += __shfl_xor_sync(0xffffffffu, nr1, o);
        nr2 += __shfl_xor_sync(0xffffffffu, nr2, o);
    }
    if (lane == 0) { g_xtn1[b] = nr1; g_xtn2[b] = nr2; }
    __syncwarp();

    if (lane < DY) {
        float y1 = b1[lane], y2 = b2[lane];
#pragma unroll
        for (int d = 0; d < D; d++) {
            y1 = fmaf(sxt[wl][0][d], W1[d * DY + lane], y1);
            y2 = fmaf(sxt[wl][1][d], W2[d * DY + lane], y2);
        }
        sy[wl][0][lane] = y1; sy[wl][1][lane] = y2;
    }
    __syncwarp();

    float best1 = 1e38f, best2 = 1e38f; int bi1 = 0x7fffffff, bi2 = 0x7fffffff;
    for (int lab = lane; lab < L; lab += 32) {
        float s1 = 0.f, s2 = 0.f;
        for (int dy = 0; dy < DY; dy++) {
            float t1 = sy[wl][0][dy] - u1[lab * DY + dy]; s1 = fmaf(t1, t1, s1);
            float t2 = sy[wl][1][dy] - u2[lab * DY + dy]; s2 = fmaf(t2, t2, s2);
        }
        if (s1 < best1) { best1 = s1; bi1 = lab; }
        if (s2 < best2) { best2 = s2; bi2 = lab; }
    }
#pragma unroll
    for (int o = 16; o; o >>= 1) {
        float ob = __shfl_xor_sync(0xffffffffu, best1, o);
        int obi  = __shfl_xor_sync(0xffffffffu, bi1, o);
        if (ob < best1 || (ob == best1 && obi < bi1)) { best1 = ob; bi1 = obi; }
        ob  = __shfl_xor_sync(0xffffffffu, best2, o);
        obi = __shfl_xor_sync(0xffffffffu, bi2, o);
        if (ob < best2 || (ob == best2 && obi < bi2)) { best2 = ob; bi2 = obi; }
    }
    if (lane == 0) { g_yidx1[b] = bi1; g_yidx2[b] = bi2; }
}

// ---------------- Pass 2 (grid.z = branch) ----------------
struct SmemP2 {
    float Qs[TQ][D + 4];
    float qn[TQ];
    float Kst[D][TI + 4];
    float kn[TI];
    float Es[TI][TQ + 4];
    float Vs[TI][36];
    float ldt[MAXL * MAXL];   // 0.01 * ldist
    int   jli[TI];
    int   yq[TQ];
};

__global__ void __launch_bounds__(256) pass2_kernel(
    const float* __restrict__ f1, const float* __restrict__ f2,
    const float* __restrict__ sl,
    const float* __restrict__ ld1, const float* __restrict__ ld2,
    const int* __restrict__ li1, const int* __restrict__ li2,
    int B, int N, int DY, int L)
{
    extern __shared__ char smraw[];
    SmemP2& sm = *reinterpret_cast<SmemP2*>(smraw);
    int t = threadIdx.x, tx = t & 15, ty = t >> 4;
    int z = blockIdx.z;
    const float* Kg  = z ? f2 : f1;
    const float* kng = z ? g_f2norm : g_f1norm;
    const float* Qg  = z ? g_xt2 : g_xt1;
    const float* qng = z ? g_xtn2 : g_xtn1;
    const float* ldm = z ? ld2 : ld1;
    const int*   li  = z ? li2 : li1;
    const int*   yix = z ? g_yidx2 : g_yidx1;

    int qbase = blockIdx.x * TQ;
    int chunk = (N + NSPLIT - 1) / NSPLIT;
    int i0base = blockIdx.y * chunk;
    int iend = min(i0base + chunk, N);

    {
        int row = t >> 2, cg = (t & 3) * 16;
        const float4* src = (const float4*)(Qg + (size_t)(qbase + row) * D + cg);
        float4* dst = (float4*)&sm.Qs[row][cg];
        dst[0] = src[0]; dst[1] = src[1]; dst[2] = src[2]; dst[3] = src[3];
        if (t < TQ) { sm.qn[t] = qng[qbase + t]; sm.yq[t] = yix[qbase + t]; }
        for (int idx = t; idx < L * L; idx += 256) sm.ldt[idx] = 0.01f * ldm[idx];
    }

    float C[4][2] = {{0.f,0.f},{0.f,0.f},{0.f,0.f},{0.f,0.f}};
    float denp[4] = {0.f, 0.f, 0.f, 0.f};

    for (int i0 = i0base; i0 < iend; i0 += TI) {
        __syncthreads();
        {
            int j = t >> 3, dg = (t & 7) * 8;
            int i = i0 + j;
            float4 a = {0,0,0,0}, b = {0,0,0,0};
            if (i < iend) {
                a = *(const float4*)(Kg + (size_t)i * D + dg);
                b = *(const float4*)(Kg + (size_t)i * D + dg + 4);
            }
            sm.Kst[dg + 0][j] = a.x; sm.Kst[dg + 1][j] = a.y;
            sm.Kst[dg + 2][j] = a.z; sm.Kst[dg + 3][j] = a.w;
            sm.Kst[dg + 4][j] = b.x; sm.Kst[dg + 5][j] = b.y;
            sm.Kst[dg + 6][j] = b.z; sm.Kst[dg + 7][j] = b.w;
            if (t < TI) {
                int ii = i0 + t;
                sm.kn[t]  = (ii < iend) ? kng[ii] : 1e30f;
                sm.jli[t] = (ii < iend) ? li[ii] : 0;
            }
        }
        { // V tile: star_labels [TI][32]
            int j = t >> 3, cg = (t & 7) * 4;
            int i = i0 + j;
            float4 v = {0,0,0,0};
            if (i < iend) v = *(const float4*)(sl + (size_t)i * DY + cg);
            *(float4*)&sm.Vs[j][cg] = v;
        }
        __syncthreads();

        float acc[4][2] = {{0.f,0.f},{0.f,0.f},{0.f,0.f},{0.f,0.f}};
#pragma unroll
        for (int d = 0; d < D; d += 4) {
            float2 b0 = *(const float2*)&sm.Kst[d + 0][tx * 2];
            float2 b1 = *(const float2*)&sm.Kst[d + 1][tx * 2];
            float2 b2 = *(const float2*)&sm.Kst[d + 2][tx * 2];
            float2 b3 = *(const float2*)&sm.Kst[d + 3][tx * 2];
#pragma unroll
            for (int qq = 0; qq < 4; qq++) {
                float4 a = *(const float4*)&sm.Qs[ty * 4 + qq][d];
                acc[qq][0] = fmaf(a.x, b0.x, fmaf(a.y, b1.x, fmaf(a.z, b2.x, fmaf(a.w, b3.x, acc[qq][0]))));
                acc[qq][1] = fmaf(a.x, b0.y, fmaf(a.y, b1.y, fmaf(a.z, b2.y, fmaf(a.w, b3.y, acc[qq][1]))));
            }
        }
#pragma unroll
        for (int jj = 0; jj < 2; jj++) {
            int j = tx * 2 + jj;
            int lrow = sm.jli[j] * L;
#pragma unroll
            for (int qq = 0; qq < 4; qq++) {
                int q = ty * 4 + qq;
                float raw = sm.qn[q] + sm.kn[j] - 2.0f * acc[qq][jj];
                float arg = fmaxf(raw, 0.0f) + sm.ldt[lrow + sm.yq[q]];
                float e = __expf(-arg);
                sm.Es[j][q] = e;
                denp[qq] += e;
            }
        }
        __syncthreads();

#pragma unroll 4
        for (int j = 0; j < TI; j++) {
            float4 ev = *(const float4*)&sm.Es[j][ty * 4];
            float2 v  = *(const float2*)&sm.Vs[j][tx * 2];
            float ee[4] = {ev.x, ev.y, ev.z, ev.w};
#pragma unroll
            for (int qq = 0; qq < 4; qq++) {
                C[qq][0] = fmaf(ee[qq], v.x, C[qq][0]);
                C[qq][1] = fmaf(ee[qq], v.y, C[qq][1]);
            }
        }
    }

#pragma unroll
    for (int qq = 0; qq < 4; qq++) {
        int q = qbase + ty * 4 + qq;
        size_t base = ((size_t)(z * NSPLIT + blockIdx.y) * B + q) * 32;
        g_pout[base + tx * 2 + 0] = C[qq][0];
        g_pout[base + tx * 2 + 1] = C[qq][1];
        float v = denp[qq];
#pragma unroll
        for (int o = 8; o; o >>= 1) v += __shfl_xor_sync(0xffffffffu, v, o);
        if (tx == 0) g_pden2[(size_t)(z * NSPLIT + blockIdx.y) * B + q] = v;
    }
}

// ---------------- K4: final combine ----------------
__global__ void final_kernel(float* __restrict__ out, int B, int DY) {
    int idx = blockIdx.x * blockDim.x + threadIdx.x;
    if (idx >= B * DY) return;
    int b = idx / DY, dy = idx % DY;
    float n1 = 0, d1 = 0, n2 = 0, d2 = 0;
#pragma unroll
    for (int s = 0; s < NSPLIT; s++) {
        n1 += g_pout[((size_t)s * B + b) * 32 + dy];
        d1 += g_pden2[(size_t)s * B + b];
        n2 += g_pout[((size_t)(NSPLIT + s) * B + b) * 32 + dy];
        d2 += g_pden2[(size_t)(NSPLIT + s) * B + b];
    }
    out[idx] = 0.5f * (n1 / d1 + n2 / d2);
}

// ---------------- launch ----------------
extern "C" void kernel_launch(void* const* d_in, const int* in_sizes, int n_in,
                              void* d_out, int out_size) {
    const float* x   = (const float*)d_in[0];
    const float* sf  = (const float*)d_in[1];
    const float* sl  = (const float*)d_in[2];
    const float* f1  = (const float*)d_in[3];
    const float* f2  = (const float*)d_in[4];
    const float* u1  = (const float*)d_in[5];
    const float* u2  = (const float*)d_in[6];
    const float* ld1 = (const float*)d_in[7];
    const float* ld2 = (const float*)d_in[8];
    const float* W1  = (const float*)d_in[9];
    const float* b1  = (const float*)d_in[10];
    const float* W2  = (const float*)d_in[11];
    const float* b2  = (const float*)d_in[12];
    const int*   li1 = (const int*)d_in[13];
    const int*   li2 = (const int*)d_in[14];

    int DY = in_sizes[10];            // 32
    int Dd = in_sizes[9] / DY;        // 64
    int B  = in_sizes[0] / Dd;        // 2048
    int N  = in_sizes[1] / Dd;        // 20000
    int L  = in_sizes[5] / DY;        // 100

    cudaFuncSetAttribute(pass1_kernel, cudaFuncAttributeMaxDynamicSharedMemorySize, (int)sizeof(SmemP1));
    cudaFuncSetAttribute(pass2_kernel, cudaFuncAttributeMaxDynamicSharedMemorySize, (int)sizeof(SmemP2));

    int total = 3 * N + B;
    norms_kernel<<<(total + 255) / 256, 256>>>(x, sf, f1, f2, B, N);

    dim3 g1(B / TQ, NSPLIT);
    pass1_kernel<<<g1, 256, sizeof(SmemP1)>>>(x, sf, f1, f2, B, N);

    mid_kernel<<<B / 8, 256>>>(f1, f2, W1, b1, W2, b2, u1, u2, B, N, DY, L);

    dim3 g2(B / TQ, NSPLIT, 2);
    pass2_kernel<<<g2, 256, sizeof(SmemP2)>>>(f1, f2, sl, ld1, ld2, li1, li2, B, N, DY, L);

    final_kernel<<<(B * DY + 255) / 256, 256>>>((float*)d_out, B, DY);
}

// round 3
// speedup vs baseline: 1.0907x; 1.0907x over previous
#include <cuda_runtime.h>
#include <cstdint>

typedef unsigned long long ull;

#define D      64
#define TQ     64
#define TI     64
#define NSPLIT 32
#define MAXB   2048
#define MAXN   20000
#define MAXL   100

// ---------------- static device scratch (16B-aligned: accessed via float4/ulonglong2) ----------------
__device__ __align__(16) float g_sfT[(size_t)D * MAXN + 64];
__device__ __align__(16) float g_f1T[(size_t)D * MAXN + 64];
__device__ __align__(16) float g_f2T[(size_t)D * MAXN + 64];
__device__ float g_xnorm[MAXB];
__device__ float g_snorm[MAXN];
__device__ float g_f1norm[MAXN];
__device__ float g_f2norm[MAXN];
__device__ int   g_match[MAXB];
__device__ __align__(16) float g_pnum[(size_t)NSPLIT * MAXB * 128];
__device__ float g_pden[(size_t)NSPLIT * MAXB];
__device__ __align__(16) float g_xt1[MAXB * D];
__device__ __align__(16) float g_xt2[MAXB * D];
__device__ float g_xtn1[MAXB];
__device__ float g_xtn2[MAXB];
__device__ int   g_yidx1[MAXB];
__device__ int   g_yidx2[MAXB];
__device__ __align__(16) float g_pout[(size_t)2 * NSPLIT * 2 * MAXB * 32];
__device__ float g_pden2[(size_t)2 * NSPLIT * MAXB];

// ---------------- f32x2 helpers ----------------
__device__ __forceinline__ ull pack2(float v) {
    ull r; asm("mov.b64 %0, {%1, %1};" : "=l"(r) : "f"(v)); return r;
}
__device__ __forceinline__ void ffma2(ull& a, ull x, ull y) {
    asm("fma.rn.f32x2 %0, %1, %2, %0;" : "+l"(a) : "l"(x), "l"(y));
}
__device__ __forceinline__ float2 u2f(ull v) {
    float2 f; asm("mov.b64 {%0, %1}, %2;" : "=f"(f.x), "=f"(f.y) : "l"(v)); return f;
}

// ---------------- K-1: transpose sf/f1/f2 to [d][i] ----------------
__global__ void transpose_kernel(const float* __restrict__ sf, const float* __restrict__ f1,
                                 const float* __restrict__ f2, int N) {
    __shared__ float tile[32][33];
    int z = blockIdx.z;
    const float* src = (z == 0) ? sf : (z == 1) ? f1 : f2;
    float* dst = (z == 0) ? g_sfT : (z == 1) ? g_f1T : g_f2T;
    int i0 = blockIdx.x * 32, d0 = blockIdx.y * 32;
    int txx = threadIdx.x, tyy = threadIdx.y;
#pragma unroll
    for (int r = tyy; r < 32; r += 8) {
        int i = i0 + r;
        tile[r][txx] = (i < N) ? src[(size_t)i * D + d0 + txx] : 0.f;
    }
    __syncthreads();
#pragma unroll
    for (int r = tyy; r < 32; r += 8) {
        int i = i0 + txx;
        if (i < N) dst[(size_t)(d0 + r) * N + i] = tile[txx][r];
    }
    // zero the 64-float pad past each transposed matrix (read by OOB tile loads)
    if (blockIdx.x == 0 && blockIdx.y == 0 && tyy == 0) {
        dst[(size_t)D * N + txx] = 0.f;
        dst[(size_t)D * N + 32 + txx] = 0.f;
    }
}

// ---------------- K0: row norms + match init ----------------
__global__ void norms_kernel(const float* __restrict__ x, const float* __restrict__ sf,
                             const float* __restrict__ f1, const float* __restrict__ f2,
                             int B, int N) {
    int r = blockIdx.x * blockDim.x + threadIdx.x;
    int total = 3 * N + B;
    if (r >= total) return;
    const float* src; float* dst; int row;
    if (r < N)            { src = sf; row = r;         dst = g_snorm; }
    else if (r < 2 * N)   { src = f1; row = r - N;     dst = g_f1norm; }
    else if (r < 3 * N)   { src = f2; row = r - 2 * N; dst = g_f2norm; }
    else                  { src = x;  row = r - 3 * N; dst = g_xnorm; g_match[row] = 0x7fffffff; }
    const float4* p = (const float4*)(src + (size_t)row * D);
    float s = 0.f;
#pragma unroll
    for (int k = 0; k < 16; k++) {
        float4 v = p[k];
        s = fmaf(v.x, v.x, fmaf(v.y, v.y, fmaf(v.z, v.z, fmaf(v.w, v.w, s))));
    }
    dst[row] = s;
}

// ---------------- QK microkernel macros ----------------
#define QK_STEP(bk, c0, c1, c2, c3)                                   \
    { ull p;                                                          \
      p = pack2(c0); ffma2(acc00, p, bk.x); ffma2(acc01, p, bk.y);    \
      p = pack2(c1); ffma2(acc10, p, bk.x); ffma2(acc11, p, bk.y);    \
      p = pack2(c2); ffma2(acc20, p, bk.x); ffma2(acc21, p, bk.y);    \
      p = pack2(c3); ffma2(acc30, p, bk.x); ffma2(acc31, p, bk.y); }

#define QK_CHUNK(SM)                                                  \
    { ulonglong2 b0 = *(const ulonglong2*)&SM.Kst[dd + 0][tx4];       \
      ulonglong2 b1 = *(const ulonglong2*)&SM.Kst[dd + 1][tx4];       \
      ulonglong2 b2 = *(const ulonglong2*)&SM.Kst[dd + 2][tx4];       \
      ulonglong2 b3 = *(const ulonglong2*)&SM.Kst[dd + 3][tx4];       \
      float4 a0 = *(const float4*)&SM.Qs[tyq + 0][dd];                \
      float4 a1 = *(const float4*)&SM.Qs[tyq + 1][dd];                \
      float4 a2 = *(const float4*)&SM.Qs[tyq + 2][dd];                \
      float4 a3 = *(const float4*)&SM.Qs[tyq + 3][dd];                \
      QK_STEP(b0, a0.x, a1.x, a2.x, a3.x);                            \
      QK_STEP(b1, a0.y, a1.y, a2.y, a3.y);                            \
      QK_STEP(b2, a0.z, a1.z, a2.z, a3.z);                            \
      QK_STEP(b3, a0.w, a1.w, a2.w, a3.w); }

// ---------------- Pass 1 ----------------
struct SmemP1 {
    float Qs[TQ][68];
    float Kst[D][68];
    float Es[TQ][68];     // [q][j]
    float Vs[TI][132];    // [j][f1(64)|f2(64)]
    float qn[TQ];
    float kn[TI];
};

#define SCORE1(A0, A1, QQ)                                             \
    { int q = tyq + QQ;                                                \
      float qv = sm.qn[q];                                             \
      float2 s0 = u2f(A0), s1 = u2f(A1);                               \
      float r0 = qv + knv.x - 2.f * s0.x;                              \
      float r1 = qv + knv.y - 2.f * s0.y;                              \
      float r2 = qv + knv.z - 2.f * s1.x;                              \
      float r3 = qv + knv.w - 2.f * s1.y;                              \
      if (r0 <= 0.f) mmin[QQ] = min(mmin[QQ], i0 + tx4 + 0);           \
      if (r1 <= 0.f) mmin[QQ] = min(mmin[QQ], i0 + tx4 + 1);           \
      if (r2 <= 0.f) mmin[QQ] = min(mmin[QQ], i0 + tx4 + 2);           \
      if (r3 <= 0.f) mmin[QQ] = min(mmin[QQ], i0 + tx4 + 3);           \
      float e0 = __expf(-fmaxf(r0, 0.f));                              \
      float e1 = __expf(-fmaxf(r1, 0.f));                              \
      float e2 = __expf(-fmaxf(r2, 0.f));                              \
      float e3 = __expf(-fmaxf(r3, 0.f));                              \
      denp[QQ] += (e0 + e1) + (e2 + e3);                               \
      *(float4*)&sm.Es[q][tx4] = make_float4(e0, e1, e2, e3); }

__global__ void __launch_bounds__(256, 2) pass1_kernel(
    const float* __restrict__ x,
    const float* __restrict__ f1, const float* __restrict__ f2,
    int B, int N, int chunk)
{
    extern __shared__ char smraw[];
    SmemP1& sm = *reinterpret_cast<SmemP1*>(smraw);
    int t = threadIdx.x, tx = t & 15, ty = t >> 4;
    int tx4 = tx * 4, tyq = ty * 4;
    int qbase = blockIdx.x * TQ;
    int i0base = blockIdx.y * chunk;
    int iend = min(i0base + chunk, N);

    {   // Q tile + norms (once)
        int row = t >> 2, cg = (t & 3) * 16;
        const float4* src = (const float4*)(x + (size_t)(qbase + row) * D + cg);
        float4* dst = (float4*)&sm.Qs[row][cg];
        dst[0] = src[0]; dst[1] = src[1]; dst[2] = src[2]; dst[3] = src[3];
        if (t < TQ) sm.qn[t] = g_xnorm[qbase + t];
    }

    ull C[4][4];
#pragma unroll
    for (int a = 0; a < 4; a++)
#pragma unroll
        for (int b = 0; b < 4; b++) C[a][b] = 0ull;
    float denp[4] = {0.f, 0.f, 0.f, 0.f};
    int mmin[4] = {0x7fffffff, 0x7fffffff, 0x7fffffff, 0x7fffffff};

    for (int i0 = i0base; i0 < iend; i0 += TI) {
        // hoisted global loads (overlap with other warps' EV of prior tile)
        int kd = t >> 2, kjseg = (t & 3) * 16;
        const float4* ksrc = (const float4*)(g_sfT + (size_t)kd * N + i0 + kjseg);
        float4 k0 = ksrc[0], k1 = ksrc[1], k2 = ksrc[2], k3 = ksrc[3];
        int vj = t >> 2, vcs = (t & 3) * 32;
        int vi = i0 + vj;
        bool vok = vi < iend;
        const float4* vrow = (const float4*)((vcs < 64) ? (f1 + (size_t)vi * D + vcs)
                                                        : (f2 + (size_t)vi * D + (vcs - 64)));
        float4 v[8];
#pragma unroll
        for (int k = 0; k < 8; k++) v[k] = vok ? vrow[k] : make_float4(0.f, 0.f, 0.f, 0.f);
        float knval = 1e30f;
        if (t < TI && i0 + t < iend) knval = g_snorm[i0 + t];

        __syncthreads();
        { float4* kdp = (float4*)&sm.Kst[kd][kjseg]; kdp[0] = k0; kdp[1] = k1; kdp[2] = k2; kdp[3] = k3; }
        { float4* vdp = (float4*)&sm.Vs[vj][vcs];
#pragma unroll
          for (int k = 0; k < 8; k++) vdp[k] = v[k]; }
        if (t < TI) sm.kn[t] = knval;
        __syncthreads();

        // QK: 4q x 4j per thread, f32x2 packed
        ull acc00 = 0, acc01 = 0, acc10 = 0, acc11 = 0,
            acc20 = 0, acc21 = 0, acc30 = 0, acc31 = 0;
#pragma unroll 4
        for (int dd = 0; dd < D; dd += 4) QK_CHUNK(sm);

        float4 knv = *(const float4*)&sm.kn[tx4];
        SCORE1(acc00, acc01, 0);
        SCORE1(acc10, acc11, 1);
        SCORE1(acc20, acc21, 2);
        SCORE1(acc30, acc31, 3);
        __syncthreads();

        // EV: C[4q][8dy as 4 ull] += E * V
#pragma unroll 2
        for (int j = 0; j < TI; j++) {
            ull e0 = pack2(sm.Es[tyq + 0][j]);
            ull e1 = pack2(sm.Es[tyq + 1][j]);
            ull e2 = pack2(sm.Es[tyq + 2][j]);
            ull e3 = pack2(sm.Es[tyq + 3][j]);
            const ull* vp = (const ull*)&sm.Vs[j][tx * 8];
            ull v0 = vp[0], v1 = vp[1], v2 = vp[2], v3 = vp[3];
            ffma2(C[0][0], e0, v0); ffma2(C[0][1], e0, v1); ffma2(C[0][2], e0, v2); ffma2(C[0][3], e0, v3);
            ffma2(C[1][0], e1, v0); ffma2(C[1][1], e1, v1); ffma2(C[1][2], e1, v2); ffma2(C[1][3], e1, v3);
            ffma2(C[2][0], e2, v0); ffma2(C[2][1], e2, v1); ffma2(C[2][2], e2, v2); ffma2(C[2][3], e2, v3);
            ffma2(C[3][0], e3, v0); ffma2(C[3][1], e3, v1); ffma2(C[3][2], e3, v2); ffma2(C[3][3], e3, v3);
        }
    }

#pragma unroll
    for (int qq = 0; qq < 4; qq++) {
        int q = qbase + tyq + qq;
        float* gp = g_pnum + ((size_t)blockIdx.y * B + q) * 128 + tx * 8;
        *(ulonglong2*)gp = make_ulonglong2(C[qq][0], C[qq][1]);
        *(ulonglong2*)(gp + 4) = make_ulonglong2(C[qq][2], C[qq][3]);
        float v = denp[qq];
#pragma unroll
        for (int o = 8; o; o >>= 1) v += __shfl_xor_sync(0xffffffffu, v, o);
        int mv = mmin[qq];
#pragma unroll
        for (int o = 8; o; o >>= 1) mv = min(mv, __shfl_xor_sync(0xffffffffu, mv, o));
        if (tx == 0) {
            g_pden[(size_t)blockIdx.y * B + q] = v;
            if (mv != 0x7fffffff) atomicMin(&g_match[q], mv);
        }
    }
}

// ---------------- K2: reduce -> xt, y = xt W + b, argmin labels ----------------
__global__ void mid_kernel(const float* __restrict__ f1, const float* __restrict__ f2,
                           const float* __restrict__ W1, const float* __restrict__ b1,
                           const float* __restrict__ W2, const float* __restrict__ b2,
                           const float* __restrict__ u1, const float* __restrict__ u2,
                           int B, int N, int DY, int L) {
    __shared__ float sxt[8][2][D];
    __shared__ float sy[8][2][32];
    int wl = threadIdx.x >> 5;
    int lane = threadIdx.x & 31;
    int b = blockIdx.x * 8 + wl;
    if (b >= B) return;

    float den = 0.f;
#pragma unroll
    for (int s = 0; s < NSPLIT; s++) den += g_pden[(size_t)s * B + b];
    int d0 = lane, d1 = lane + 32;
    float n10 = 0, n11 = 0, n20 = 0, n21 = 0;
#pragma unroll
    for (int s = 0; s < NSPLIT; s++) {
        const float* p = g_pnum + ((size_t)s * B + b) * 128;
        n10 += p[d0]; n11 += p[d1]; n20 += p[64 + d0]; n21 += p[64 + d1];
    }
    float inv = 1.0f / den;
    float x10 = n10 * inv, x11 = n11 * inv, x20 = n20 * inv, x21 = n21 * inv;
    int m = g_match[b];
    if (m < N) {
        x10 = f1[(size_t)m * D + d0]; x11 = f1[(size_t)m * D + d1];
        x20 = f2[(size_t)m * D + d0]; x21 = f2[(size_t)m * D + d1];
    }
    g_xt1[b * D + d0] = x10; g_xt1[b * D + d1] = x11;
    g_xt2[b * D + d0] = x20; g_xt2[b * D + d1] = x21;
    sxt[wl][0][d0] = x10; sxt[wl][0][d1] = x11;
    sxt[wl][1][d0] = x20; sxt[wl][1][d1] = x21;
    float nr1 = x10 * x10 + x11 * x11;
    float nr2 = x20 * x20 + x21 * x21;
#pragma unroll
    for (int o = 16; o; o >>= 1) {
        nr1 += __shfl_xor_sync(0xffffffffu, nr1, o);
        nr2 += __shfl_xor_sync(0xffffffffu, nr2, o);
    }
    if (lane == 0) { g_xtn1[b] = nr1; g_xtn2[b] = nr2; }
    __syncwarp();

    if (lane < DY) {
        float y1 = b1[lane], y2 = b2[lane];
#pragma unroll
        for (int d = 0; d < D; d++) {
            y1 = fmaf(sxt[wl][0][d], W1[d * DY + lane], y1);
            y2 = fmaf(sxt[wl][1][d], W2[d * DY + lane], y2);
        }
        sy[wl][0][lane] = y1; sy[wl][1][lane] = y2;
    }
    __syncwarp();

    float best1 = 1e38f, best2 = 1e38f; int bi1 = 0x7fffffff, bi2 = 0x7fffffff;
    for (int lab = lane; lab < L; lab += 32) {
        float s1 = 0.f, s2 = 0.f;
        for (int dy = 0; dy < DY; dy++) {
            float t1 = sy[wl][0][dy] - u1[lab * DY + dy]; s1 = fmaf(t1, t1, s1);
            float t2 = sy[wl][1][dy] - u2[lab * DY + dy]; s2 = fmaf(t2, t2, s2);
        }
        if (s1 < best1) { best1 = s1; bi1 = lab; }
        if (s2 < best2) { best2 = s2; bi2 = lab; }
    }
#pragma unroll
    for (int o = 16; o; o >>= 1) {
        float ob = __shfl_xor_sync(0xffffffffu, best1, o);
        int obi  = __shfl_xor_sync(0xffffffffu, bi1, o);
        if (ob < best1 || (ob == best1 && obi < bi1)) { best1 = ob; bi1 = obi; }
        ob  = __shfl_xor_sync(0xffffffffu, best2, o);
        obi = __shfl_xor_sync(0xffffffffu, bi2, o);
        if (ob < best2 || (ob == best2 && obi < bi2)) { best2 = ob; bi2 = obi; }
    }
    if (lane == 0) { g_yidx1[b] = bi1; g_yidx2[b] = bi2; }
}

// ---------------- Pass 2 ----------------
struct SmemP2 {
    float Qs[TQ][68];
    float Kst[D][68];
    float Es[TQ][68];     // [q][j]
    float Vs[TI][36];     // star_labels
    float ldt[MAXL * MAXL];
    float qn[TQ];
    float kn[TI];
    int   jli[TI];        // label_indices * L (premultiplied)
    int   yq[TQ];
};

#define SCORE2(A0, A1, QQ)                                                      \
    { int q = tyq + QQ;                                                         \
      float qv = sm.qn[q]; int yv = sm.yq[q];                                   \
      float2 s0 = u2f(A0), s1 = u2f(A1);                                        \
      float r0 = fmaxf(qv + knv.x - 2.f * s0.x, 0.f) + sm.ldt[jl0 + yv];        \
      float r1 = fmaxf(qv + knv.y - 2.f * s0.y, 0.f) + sm.ldt[jl1 + yv];        \
      float r2 = fmaxf(qv + knv.z - 2.f * s1.x, 0.f) + sm.ldt[jl2 + yv];        \
      float r3 = fmaxf(qv + knv.w - 2.f * s1.y, 0.f) + sm.ldt[jl3 + yv];        \
      float e0 = __expf(-r0);                                                   \
      float e1 = __expf(-r1);                                                   \
      float e2 = __expf(-r2);                                                   \
      float e3 = __expf(-r3);                                                   \
      denp[QQ] += (e0 + e1) + (e2 + e3);                                        \
      *(float4*)&sm.Es[q][tx4] = make_float4(e0, e1, e2, e3); }

__global__ void __launch_bounds__(256, 2) pass2_kernel(
    const float* __restrict__ sl,
    const float* __restrict__ ld1, const float* __restrict__ ld2,
    const int* __restrict__ li1, const int* __restrict__ li2,
    int B, int N, int L, int chunk)
{
    extern __shared__ char smraw[];
    SmemP2& sm = *reinterpret_cast<SmemP2*>(smraw);
    int t = threadIdx.x, tx = t & 15, ty = t >> 4;
    int tx4 = tx * 4, tyq = ty * 4;
    int z = blockIdx.z;
    const float* KT  = z ? g_f2T : g_f1T;
    const float* kng = z ? g_f2norm : g_f1norm;
    const float* Qg  = z ? g_xt2 : g_xt1;
    const float* qng = z ? g_xtn2 : g_xtn1;
    const float* ldm = z ? ld2 : ld1;
    const int*   li  = z ? li2 : li1;
    const int*   yix = z ? g_yidx2 : g_yidx1;

    int qbase = blockIdx.x * TQ;
    int i0base = blockIdx.y * chunk;
    int iend = min(i0base + chunk, N);

    {
        int row = t >> 2, cg = (t & 3) * 16;
        const float4* src = (const float4*)(Qg + (size_t)(qbase + row) * D + cg);
        float4* dst = (float4*)&sm.Qs[row][cg];
        dst[0] = src[0]; dst[1] = src[1]; dst[2] = src[2]; dst[3] = src[3];
        if (t < TQ) { sm.qn[t] = qng[qbase + t]; sm.yq[t] = yix[qbase + t]; }
        for (int idx = t; idx < L * L; idx += 256) sm.ldt[idx] = 0.01f * ldm[idx];
    }

    int jh = (tx >> 3) * 32;      // EV j-half
    int dyb = (tx & 7) * 4;       // EV dy base (4 floats = 2 ull)
    ull C[4][2];
#pragma unroll
    for (int a = 0; a < 4; a++) { C[a][0] = 0ull; C[a][1] = 0ull; }
    float denp[4] = {0.f, 0.f, 0.f, 0.f};

    for (int i0 = i0base; i0 < iend; i0 += TI) {
        int kd = t >> 2, kjseg = (t & 3) * 16;
        const float4* ksrc = (const float4*)(KT + (size_t)kd * N + i0 + kjseg);
        float4 k0 = ksrc[0], k1 = ksrc[1], k2 = ksrc[2], k3 = ksrc[3];
        int vj = t >> 2, vc = (t & 3) * 8;
        int vi = i0 + vj;
        bool vok = vi < iend;
        const float4* vrow = (const float4*)(sl + (size_t)vi * 32 + vc);
        float4 v0 = vok ? vrow[0] : make_float4(0.f, 0.f, 0.f, 0.f);
        float4 v1 = vok ? vrow[1] : make_float4(0.f, 0.f, 0.f, 0.f);
        float knval = 1e30f; int jliv = 0;
        if (t < TI && i0 + t < iend) { knval = kng[i0 + t]; jliv = li[i0 + t] * L; }

        __syncthreads();
        { float4* kdp = (float4*)&sm.Kst[kd][kjseg]; kdp[0] = k0; kdp[1] = k1; kdp[2] = k2; kdp[3] = k3; }
        { float4* vdp = (float4*)&sm.Vs[vj][vc]; vdp[0] = v0; vdp[1] = v1; }
        if (t < TI) { sm.kn[t] = knval; sm.jli[t] = jliv; }
        __syncthreads();

        ull acc00 = 0, acc01 = 0, acc10 = 0, acc11 = 0,
            acc20 = 0, acc21 = 0, acc30 = 0, acc31 = 0;
#pragma unroll 4
        for (int dd = 0; dd < D; dd += 4) QK_CHUNK(sm);

        float4 knv = *(const float4*)&sm.kn[tx4];
        int jl0 = sm.jli[tx4 + 0], jl1 = sm.jli[tx4 + 1],
            jl2 = sm.jli[tx4 + 2], jl3 = sm.jli[tx4 + 3];
        SCORE2(acc00, acc01, 0);
        SCORE2(acc10, acc11, 1);
        SCORE2(acc20, acc21, 2);
        SCORE2(acc30, acc31, 3);
        __syncthreads();

        // EV: j split in halves across tx bit 3; dy pairs across tx&7
#pragma unroll 4
        for (int jj = 0; jj < 32; jj++) {
            int j = jh + jj;
            ulonglong2 vv = *(const ulonglong2*)&sm.Vs[j][dyb];
            ull e0 = pack2(sm.Es[tyq + 0][j]);
            ull e1 = pack2(sm.Es[tyq + 1][j]);
            ull e2 = pack2(sm.Es[tyq + 2][j]);
            ull e3 = pack2(sm.Es[tyq + 3][j]);
            ffma2(C[0][0], e0, vv.x); ffma2(C[0][1], e0, vv.y);
            ffma2(C[1][0], e1, vv.x); ffma2(C[1][1], e1, vv.y);
            ffma2(C[2][0], e2, vv.x); ffma2(C[2][1], e2, vv.y);
            ffma2(C[3][0], e3, vv.x); ffma2(C[3][1], e3, vv.y);
        }
    }

    int half = tx >> 3;
#pragma unroll
    for (int qq = 0; qq < 4; qq++) {
        int q = qbase + tyq + qq;
        size_t sidx = ((size_t)(z * NSPLIT + blockIdx.y)) * 2 + half;
        float* gp = g_pout + (sidx * B + q) * 32 + dyb;
        *(ulonglong2*)gp = make_ulonglong2(C[qq][0], C[qq][1]);
        float v = denp[qq];
#pragma unroll
        for (int o = 8; o; o >>= 1) v += __shfl_xor_sync(0xffffffffu, v, o);
        if (tx == 0) g_pden2[(size_t)(z * NSPLIT + blockIdx.y) * B + q] = v;
    }
}

// ---------------- K4: final combine ----------------
__global__ void final_kernel(float* __restrict__ out, int B, int DY) {
    int idx = blockIdx.x * blockDim.x + threadIdx.x;
    if (idx >= B * DY) return;
    int b = idx >> 5, dy = idx & 31;
    float n1 = 0, d1 = 0, n2 = 0, d2 = 0;
#pragma unroll
    for (int s = 0; s < NSPLIT; s++) {
        d1 += g_pden2[(size_t)s * B + b];
        d2 += g_pden2[(size_t)(NSPLIT + s) * B + b];
        n1 += g_pout[(((size_t)s * 2 + 0) * B + b) * 32 + dy]
            + g_pout[(((size_t)s * 2 + 1) * B + b) * 32 + dy];
        n2 += g_pout[(((size_t)(NSPLIT + s) * 2 + 0) * B + b) * 32 + dy]
            + g_pout[(((size_t)(NSPLIT + s) * 2 + 1) * B + b) * 32 + dy];
    }
    out[idx] = 0.5f * (n1 / d1 + n2 / d2);
}

// ---------------- launch ----------------
extern "C" void kernel_launch(void* const* d_in, const int* in_sizes, int n_in,
                              void* d_out, int out_size) {
    const float* x   = (const float*)d_in[0];
    const float* sf  = (const float*)d_in[1];
    const float* sl  = (const float*)d_in[2];
    const float* f1  = (const float*)d_in[3];
    const float* f2  = (const float*)d_in[4];
    const float* u1  = (const float*)d_in[5];
    const float* u2  = (const float*)d_in[6];
    const float* ld1 = (const float*)d_in[7];
    const float* ld2 = (const float*)d_in[8];
    const float* W1  = (const float*)d_in[9];
    const float* b1  = (const float*)d_in[10];
    const float* W2  = (const float*)d_in[11];
    const float* b2  = (const float*)d_in[12];
    const int*   li1 = (const int*)d_in[13];
    const int*   li2 = (const int*)d_in[14];

    int DY = in_sizes[10];            // 32
    int Dd = in_sizes[9] / DY;        // 64
    int B  = in_sizes[0] / Dd;        // 2048
    int N  = in_sizes[1] / Dd;        // 20000
    int L  = in_sizes[5] / DY;        // 100

    // per-split chunk rounded to TI so every tile base i0 is 64-aligned
    // (keeps the float4 loads from the [d][i]-transposed matrices aligned)
    int chunk = ((N + NSPLIT - 1) / NSPLIT + TI - 1) / TI * TI;

    cudaFuncSetAttribute(pass1_kernel, cudaFuncAttributeMaxDynamicSharedMemorySize, (int)sizeof(SmemP1));
    cudaFuncSetAttribute(pass2_kernel, cudaFuncAttributeMaxDynamicSharedMemorySize, (int)sizeof(SmemP2));

    transpose_kernel<<<dim3((N + 31) / 32, D / 32, 3), dim3(32, 8)>>>(sf, f1, f2, N);

    int total = 3 * N + B;
    norms_kernel<<<(total + 255) / 256, 256>>>(x, sf, f1, f2, B, N);

    pass1_kernel<<<dim3(B / TQ, NSPLIT), 256, sizeof(SmemP1)>>>(x, f1, f2, B, N, chunk);

    mid_kernel<<<B / 8, 256>>>(f1, f2, W1, b1, W2, b2, u1, u2, B, N, DY, L);

    pass2_kernel<<<dim3(B / TQ, NSPLIT, 2), 256, sizeof(SmemP2)>>>(sl, ld1, ld2, li1, li2, B, N, L, chunk);

    final_kernel<<<(B * DY + 255) / 256, 256>>>((float*)d_out, B, DY);
}